// round 8
// baseline (speedup 1.0000x reference)
#include <cuda_runtime.h>
#include <cuda_fp16.h>

#define NB 2
#define HH 512
#define WW 512
#define MASK 511
#define HW (HH*WW)

#define LANES 32        // threads per row; thread owns cols (c, c+32); warp = one row
#define TYv 8
#define RPT 2
#define TILE_W 64
#define TILE_H 16       // TYv * RPT
#define NTHR (LANES*TYv)   // 256

#define RC_ROWS 20      // template rows -2..17
#define YP_ROWS 30      // y rows -7..22
#define YP_COLS 46      // y col (.x): -7..38 ; (.y) = +32
#define BP_ROWS 26      // B/x rows -5..20
#define BP_COLS 42      // col (.x): -5..36 ; (.y) = +32

#define RC_STRIDE (11*LANES)   // 352 u64 per rc row

// offsets in u64 units
#define OFF_RC 0
#define OFF_YP (RC_ROWS*RC_STRIDE)            // 7040
#define OFF_BP (OFF_YP + YP_ROWS*YP_COLS)     // 8420
#define OFF_XH (OFF_BP + BP_ROWS*BP_COLS)     // 9512
#define XH_PLANE (BP_ROWS*BP_COLS)            // 1092 u32 per channel
#define SMEM_U64 (OFF_XH + (3*XH_PLANE + 1)/2)  // 9512 + 1638 = 11150
#define SMEM_BYTES (SMEM_U64*8)                 // 89200

typedef unsigned long long u64;

__device__ __forceinline__ float lo_(u64 v){ return __uint_as_float((unsigned)v); }
__device__ __forceinline__ float hi_(u64 v){ return __uint_as_float((unsigned)(v >> 32)); }
__device__ __forceinline__ u64 pk_(float a, float b){ u64 r; asm("mov.b64 %0, {%1, %2};" : "=l"(r) : "f"(a), "f"(b)); return r; }
__device__ __forceinline__ u64 fma2_(u64 a, u64 b, u64 c){ u64 d; asm("fma.rn.f32x2 %0, %1, %2, %3;" : "=l"(d) : "l"(a), "l"(b), "l"(c)); return d; }
__device__ __forceinline__ u64 add2_(u64 a, u64 b){ u64 d; asm("add.rn.f32x2 %0, %1, %2;" : "=l"(d) : "l"(a), "l"(b)); return d; }
__device__ __forceinline__ u64 mul2_(u64 a, u64 b){ u64 d; asm("mul.rn.f32x2 %0, %1, %2;" : "=l"(d) : "l"(a), "l"(b)); return d; }
__device__ __forceinline__ float fsqrt_a(float x){ float y; asm("sqrt.approx.f32 %0, %1;" : "=f"(y) : "f"(x)); return y; }
__device__ __forceinline__ float fex2_a (float x){ float y; asm("ex2.approx.f32 %0, %1;"  : "=f"(y) : "f"(x)); return y; }
__device__ __forceinline__ float frcp_a (float x){ float y; asm("rcp.approx.f32 %0, %1;"  : "=f"(y) : "f"(x)); return y; }

#define NEG2_2 0xC0000000C0000000ULL   // {-2.f, -2.f}
#define NEG1_2 0xBF800000BF800000ULL   // {-1.f, -1.f}

__global__ void __launch_bounds__(NTHR, 2) nlm_kernel(const float* __restrict__ x,
                                                      float* __restrict__ out){
    extern __shared__ u64 smem[];
    u64* rcS = smem + OFF_RC;              // [rr][s][lane]; becomes C in-place
    u64* sYp = smem + OFF_YP;              // [r][jj] packed luminance
    u64* sBp = smem + OFF_BP;              // [rb][jj] box5x5(y^2)
    unsigned* xh = (unsigned*)(smem + OFF_XH);  // [ch][rb][jj] half2 x
    u64* sHp = smem + OFF_RC;              // transient alias: hbox(y^2) 30x42

    const int n   = blockIdx.z;
    const int c0  = blockIdx.x * TILE_W;
    const int r0  = blockIdx.y * TILE_H;
    const int tid = threadIdx.y * LANES + threadIdx.x;
    const float* xb = x + (size_t)n*3*HW;

    // ---- sYp: packed clipped luminance, pair {col, col+32} ----
    for (int i = tid; i < YP_ROWS*YP_COLS; i += NTHR){
        int r = i / YP_COLS, jj = i - r*YP_COLS;
        int base = ((r0 + r - 7) & MASK) << 9;
        int gx = base | ((c0 + jj - 7) & MASK);
        int gy = base | ((c0 + jj + 25) & MASK);
        float l0 = 0.299f*__saturatef(xb[gx]) + 0.587f*__saturatef(xb[HW+gx]) + 0.114f*__saturatef(xb[2*HW+gx]);
        float l1 = 0.299f*__saturatef(xb[gy]) + 0.587f*__saturatef(xb[HW+gy]) + 0.114f*__saturatef(xb[2*HW+gy]);
        sYp[i] = pk_(l0, l1);
    }
    __syncthreads();
    // ---- sHp: horizontal box5 of y^2 (packed), transient in rcS space ----
    for (int i = tid; i < YP_ROWS*BP_COLS; i += NTHR){
        int r = i / BP_COLS, jj = i - r*BP_COLS;
        const u64* p = &sYp[r*YP_COLS + jj];
        u64 a = mul2_(p[0], p[0]);
        a = fma2_(p[1], p[1], a);
        a = fma2_(p[2], p[2], a);
        a = fma2_(p[3], p[3], a);
        a = fma2_(p[4], p[4], a);
        sHp[r*BP_COLS + jj] = a;
    }
    __syncthreads();
    // ---- sBp: vertical box5 of sHp ; xh: packed half2 raw x ----
    for (int i = tid; i < BP_ROWS*BP_COLS; i += NTHR){
        int rb = i / BP_COLS, jj = i - rb*BP_COLS;
        const u64* p = &sHp[rb*BP_COLS + jj];
        u64 bsum = add2_(add2_(add2_(p[0], p[BP_COLS]), add2_(p[2*BP_COLS], p[3*BP_COLS])), p[4*BP_COLS]);
        int base = ((r0 + rb - 5) & MASK) << 9;
        int gx = base | ((c0 + jj - 5) & MASK);
        int gy = base | ((c0 + jj + 27) & MASK);
        __half2 h0 = __floats2half2_rn(xb[gx],      xb[gy]);
        __half2 h1 = __floats2half2_rn(xb[HW+gx],   xb[HW+gy]);
        __half2 h2 = __floats2half2_rn(xb[2*HW+gx], xb[2*HW+gy]);
        xh[i]              = *(unsigned*)&h0;
        xh[XH_PLANE + i]   = *(unsigned*)&h1;
        xh[2*XH_PLANE + i] = *(unsigned*)&h2;
        // write B AFTER reading sHp neighbors is unsafe if another thread still reads?
        // sBp is a different region than sHp(rcS) -> safe.
        sBp[i] = bsum;
    }
    __syncthreads();

    const int lx   = threadIdx.x;
    const int trow = threadIdx.y * RPT;
    const float KEXP = -0.48089834696298783f;   // -1/(3*ln2)

    u64 Bp2[RPT];
    #pragma unroll
    for (int j = 0; j < RPT; j++)
        Bp2[j] = sBp[(trow+j+5)*BP_COLS + lx + 5];

    u64 aw2[RPT], a02[RPT], a12[RPT], a22[RPT];
    #pragma unroll
    for (int j = 0; j < RPT; j++){ aw2[j]=0; a02[j]=0; a12[j]=0; a22[j]=0; }

    #pragma unroll 1
    for (int sy = -5; sy <= 5; ++sy){
        // ---- Phase A: cooperative row correlations into rcS ----
        for (int t = tid; t < RC_ROWS*LANES; t += NTHR){
            int rr = t >> 5, cl = t & 31;
            const u64* cenp = &sYp[(rr+5)*YP_COLS + cl + 5];
            const u64* shp  = &sYp[(rr+5+sy)*YP_COLS + cl];
            u64 cen[5], sh[15];
            #pragma unroll
            for (int k = 0; k < 5; k++)  cen[k] = cenp[k];
            #pragma unroll
            for (int q = 0; q < 15; q++) sh[q]  = shp[q];
            u64* dst = &rcS[rr*RC_STRIDE + cl];
            #pragma unroll
            for (int s = 0; s < 11; s++){
                u64 r = mul2_(cen[0], sh[s]);
                r = fma2_(cen[1], sh[s+1], r);
                r = fma2_(cen[2], sh[s+2], r);
                r = fma2_(cen[3], sh[s+3], r);
                r = fma2_(cen[4], sh[s+4], r);
                dst[s*LANES] = r;
            }
        }
        __syncthreads();

        // ---- Phase A2: in-place vertical 5-sum walker per (s,lane) column ----
        // After this, rcS[rw][s][lane] (rw=0..15) holds C for output row rw.
        for (int t = tid; t < 11*LANES; t += NTHR){
            int s = t >> 5, cl = t & 31;
            u64* col = &rcS[s*LANES + cl];
            u64 ring[5];
            #pragma unroll
            for (int k = 0; k < 5; k++) ring[k] = col[k*RC_STRIDE];
            u64 sum = add2_(add2_(add2_(ring[0], ring[1]), add2_(ring[2], ring[3])), ring[4]);
            col[0] = sum;
            #pragma unroll
            for (int rw = 1; rw < 16; rw++){
                u64 nv = col[(rw+4)*RC_STRIDE];
                sum = fma2_(ring[(rw-1)%5], NEG1_2, add2_(sum, nv));
                ring[(rw-1)%5] = nv;
                col[rw*RC_STRIDE] = sum;
            }
        }
        __syncthreads();

        // ---- Phase B: weights + accumulation ----
        #pragma unroll
        for (int j = 0; j < RPT; j++){
            const u64* Crow = &rcS[(trow+j)*RC_STRIDE + lx];
            const int br = trow + j + sy + 5;
            const u64* Brow = &sBp[br*BP_COLS + lx];
            u64 w2[11];
            #pragma unroll
            for (int s = 0; s < 11; s++){
                u64 D2 = fma2_(Crow[s*LANES], NEG2_2, add2_(Bp2[j], Brow[s]));
                float d0 = fmaxf(lo_(D2), 0.f);
                float d1 = fmaxf(hi_(D2), 0.f);
                float w0 = fex2_a(fsqrt_a(d0) * KEXP);
                float w1 = fex2_a(fsqrt_a(d1) * KEXP);
                u64 w = pk_(w0, w1);
                w2[s] = w;
                aw2[j] = add2_(aw2[j], w);
            }
            #pragma unroll
            for (int ch = 0; ch < 3; ch++){
                const unsigned* Xrow = &xh[ch*XH_PLANE + br*BP_COLS + lx];
                u64 acc = (ch==0) ? a02[j] : (ch==1) ? a12[j] : a22[j];
                #pragma unroll
                for (int s = 0; s < 11; s++){
                    unsigned hx = Xrow[s];
                    float2 xv = __half22float2(*reinterpret_cast<const __half2*>(&hx));
                    acc = fma2_(w2[s], pk_(xv.x, xv.y), acc);
                }
                if (ch==0) a02[j] = acc; else if (ch==1) a12[j] = acc; else a22[j] = acc;
            }
        }
        __syncthreads();   // rcS reused next sy
    }

    // ---- epilogue: columns (c0+lx, c0+lx+32) ----
    #pragma unroll
    for (int j = 0; j < RPT; j++){
        float rw0 = frcp_a(lo_(aw2[j]));
        float rw1 = frcp_a(hi_(aw2[j]));
        int gr = r0 + trow + j;
        size_t o = (size_t)n*3*HW + ((size_t)gr << 9) + c0 + lx;
        out[o]           = __saturatef(lo_(a02[j])*rw0);
        out[o+32]        = __saturatef(hi_(a02[j])*rw1);
        out[o+HW]        = __saturatef(lo_(a12[j])*rw0);
        out[o+HW+32]     = __saturatef(hi_(a12[j])*rw1);
        out[o+2*HW]      = __saturatef(lo_(a22[j])*rw0);
        out[o+2*HW+32]   = __saturatef(hi_(a22[j])*rw1);
    }
}

extern "C" void kernel_launch(void* const* d_in, const int* in_sizes, int n_in,
                              void* d_out, int out_size){
    const float* x = (const float*)d_in[0];
    float* out = (float*)d_out;
    (void)in_sizes; (void)n_in; (void)out_size;

    cudaFuncSetAttribute(nlm_kernel, cudaFuncAttributeMaxDynamicSharedMemorySize, SMEM_BYTES);

    dim3 grid(WW/TILE_W, HH/TILE_H, NB);   // 8 x 32 x 2
    dim3 block(LANES, TYv);                // 256 threads
    nlm_kernel<<<grid, block, SMEM_BYTES>>>(x, out);
}

// round 9
// speedup vs baseline: 1.8994x; 1.8994x over previous
#include <cuda_runtime.h>
#include <cuda_fp16.h>

#define NB 2
#define HH 512
#define WW 512
#define MASK 511
#define HW (HH*WW)

#define LANES 16        // threads per row; thread owns cols (c, c+16)
#define TYv 8
#define RPT 2
#define TILE_W 32
#define TILE_H 16       // TYv * RPT
#define NTHR (LANES*TYv)

#define RC_ROWS 20      // template rows -2..17
#define YP_ROWS 30      // y rows -7..22
#define YP_COLS 30      // y col-pair index: logical col -7..22 (.x), +16 (.y)
#define BP_ROWS 26      // B/x rows -5..20
#define BP_COLS 26      // col-pair index: logical col -5..20 (.x), +16 (.y)

// offsets in u64 units
#define OFF_RC 0
#define OFF_YP (RC_ROWS*11*LANES)              // 3520
#define OFF_BP (OFF_YP + YP_ROWS*YP_COLS)      // 4420
#define OFF_XH (OFF_BP + BP_ROWS*BP_COLS)      // 5096
#define XH_PLANE (BP_ROWS*BP_COLS)             // 676 u32 per channel
#define SMEM_U64 (OFF_XH + (3*XH_PLANE + 1)/2) // 5096 + 1014 = 6110
#define SMEM_BYTES (SMEM_U64*8)                // 48880

typedef unsigned long long u64;

__device__ __forceinline__ float lo_(u64 v){ return __uint_as_float((unsigned)v); }
__device__ __forceinline__ float hi_(u64 v){ return __uint_as_float((unsigned)(v >> 32)); }
__device__ __forceinline__ u64 pk_(float a, float b){ u64 r; asm("mov.b64 %0, {%1, %2};" : "=l"(r) : "f"(a), "f"(b)); return r; }
__device__ __forceinline__ u64 fma2_(u64 a, u64 b, u64 c){ u64 d; asm("fma.rn.f32x2 %0, %1, %2, %3;" : "=l"(d) : "l"(a), "l"(b), "l"(c)); return d; }
__device__ __forceinline__ u64 add2_(u64 a, u64 b){ u64 d; asm("add.rn.f32x2 %0, %1, %2;" : "=l"(d) : "l"(a), "l"(b)); return d; }
__device__ __forceinline__ u64 mul2_(u64 a, u64 b){ u64 d; asm("mul.rn.f32x2 %0, %1, %2;" : "=l"(d) : "l"(a), "l"(b)); return d; }
__device__ __forceinline__ float fsqrt_a(float x){ float y; asm("sqrt.approx.f32 %0, %1;" : "=f"(y) : "f"(x)); return y; }
__device__ __forceinline__ float fex2_a (float x){ float y; asm("ex2.approx.f32 %0, %1;"  : "=f"(y) : "f"(x)); return y; }
__device__ __forceinline__ float frcp_a (float x){ float y; asm("rcp.approx.f32 %0, %1;"  : "=f"(y) : "f"(x)); return y; }

#define NEG2_2 0xC0000000C0000000ULL   // {-2.f, -2.f}
#define NEG1_2 0xBF800000BF800000ULL   // {-1.f, -1.f}

__global__ void __launch_bounds__(NTHR, 4) nlm_kernel(const float* __restrict__ x,
                                                      float* __restrict__ out){
    extern __shared__ u64 smem[];
    u64* rcS = smem + OFF_RC;     // [rr][s][lane]
    u64* sYp = smem + OFF_YP;     // [r][jj] packed clipped luminance
    u64* sBp = smem + OFF_BP;     // [rb][jj] box5x5(y^2)
    unsigned* xh = (unsigned*)(smem + OFF_XH);  // [ch][rb][jj] half2 x
    u64* sHp = smem + OFF_RC;     // alias: transient hbox(y^2), [r][jj] 30x26

    const int n   = blockIdx.z;
    const int c0  = blockIdx.x * TILE_W;
    const int r0  = blockIdx.y * TILE_H;
    const int tid = threadIdx.y * LANES + threadIdx.x;
    const float* xb = x + (size_t)n*3*HW;

    // ---- sYp: packed clipped luminance, pair {col, col+16} ----
    for (int i = tid; i < YP_ROWS*YP_COLS; i += NTHR){
        int r = i / YP_COLS, jj = i - r*YP_COLS;
        int base = ((r0 + r - 7) & MASK) << 9;
        int gx = base | ((c0 + jj - 7) & MASK);
        int gy = base | ((c0 + jj + 9) & MASK);
        float l0 = 0.299f*__saturatef(xb[gx]) + 0.587f*__saturatef(xb[HW+gx]) + 0.114f*__saturatef(xb[2*HW+gx]);
        float l1 = 0.299f*__saturatef(xb[gy]) + 0.587f*__saturatef(xb[HW+gy]) + 0.114f*__saturatef(xb[2*HW+gy]);
        sYp[i] = pk_(l0, l1);
    }
    __syncthreads();
    // ---- sHp: horizontal box5 of y^2 (packed), transient in rcS space ----
    for (int i = tid; i < YP_ROWS*BP_COLS; i += NTHR){
        int r = i / BP_COLS, jj = i - r*BP_COLS;
        const u64* p = &sYp[r*YP_COLS + jj];
        u64 a = mul2_(p[0], p[0]);
        a = fma2_(p[1], p[1], a);
        a = fma2_(p[2], p[2], a);
        a = fma2_(p[3], p[3], a);
        a = fma2_(p[4], p[4], a);
        sHp[r*BP_COLS + jj] = a;
    }
    __syncthreads();
    // ---- sBp: vertical box5 of sHp ; xh: packed half2 raw x ----
    for (int i = tid; i < BP_ROWS*BP_COLS; i += NTHR){
        int rb = i / BP_COLS, jj = i - rb*BP_COLS;
        const u64* p = &sHp[rb*BP_COLS + jj];
        u64 bsum = add2_(add2_(add2_(p[0], p[BP_COLS]), add2_(p[2*BP_COLS], p[3*BP_COLS])), p[4*BP_COLS]);
        int base = ((r0 + rb - 5) & MASK) << 9;
        int gx = base | ((c0 + jj - 5) & MASK);
        int gy = base | ((c0 + jj + 11) & MASK);
        __half2 h0 = __floats2half2_rn(xb[gx],      xb[gy]);
        __half2 h1 = __floats2half2_rn(xb[HW+gx],   xb[HW+gy]);
        __half2 h2 = __floats2half2_rn(xb[2*HW+gx], xb[2*HW+gy]);
        xh[i]              = *(unsigned*)&h0;
        xh[XH_PLANE + i]   = *(unsigned*)&h1;
        xh[2*XH_PLANE + i] = *(unsigned*)&h2;
        sBp[i] = bsum;   // sBp disjoint from sHp(rcS) region -> safe before barrier
    }
    __syncthreads();

    const int lx   = threadIdx.x;
    const int trow = threadIdx.y * RPT;
    const float KEXP = -0.48089834696298783f;   // -1/(3*ln2)

    u64 Bp2[RPT];
    #pragma unroll
    for (int j = 0; j < RPT; j++)
        Bp2[j] = sBp[(trow+j+5)*BP_COLS + lx + 5];

    u64 aw2[RPT], a02[RPT], a12[RPT], a22[RPT];
    #pragma unroll
    for (int j = 0; j < RPT; j++){ aw2[j]=0; a02[j]=0; a12[j]=0; a22[j]=0; }

    #pragma unroll 1
    for (int sy = -5; sy <= 5; ++sy){
        // ---- Phase A: cooperative row correlations into rcS ----
        for (int t = tid; t < RC_ROWS*LANES; t += NTHR){
            int rr = t / LANES, cl = t - rr*LANES;
            const u64* cenp = &sYp[(rr+5)*YP_COLS + cl + 5];
            const u64* shp  = &sYp[(rr+5+sy)*YP_COLS + cl];
            u64 cen[5], sh[15];
            #pragma unroll
            for (int k = 0; k < 5; k++)  cen[k] = cenp[k];
            #pragma unroll
            for (int q = 0; q < 15; q++) sh[q]  = shp[q];
            u64* dst = &rcS[rr*11*LANES + cl];
            #pragma unroll
            for (int s = 0; s < 11; s++){
                u64 r = mul2_(cen[0], sh[s]);
                r = fma2_(cen[1], sh[s+1], r);
                r = fma2_(cen[2], sh[s+2], r);
                r = fma2_(cen[3], sh[s+3], r);
                r = fma2_(cen[4], sh[s+4], r);
                dst[s*LANES] = r;
            }
        }
        __syncthreads();

        // ---- Phase B: sliding C window + weights + accumulation ----
        u64 C2[11];
        {
            const u64* p = &rcS[trow*11*LANES + lx];
            #pragma unroll
            for (int s = 0; s < 11; s++){
                u64 c = add2_(p[s*LANES], p[(11+s)*LANES]);
                c = add2_(c, p[(22+s)*LANES]);
                c = add2_(c, p[(33+s)*LANES]);
                C2[s] = add2_(c, p[(44+s)*LANES]);
            }
        }
        #pragma unroll
        for (int j = 0; j < RPT; j++){
            if (j == 1){
                const u64* pn = &rcS[(trow+5)*11*LANES + lx];
                const u64* po = &rcS[trow*11*LANES + lx];
                #pragma unroll
                for (int s = 0; s < 11; s++)
                    C2[s] = fma2_(po[s*LANES], NEG1_2, add2_(C2[s], pn[s*LANES]));
            }
            const int br = trow + j + sy + 5;
            const u64* Brow = &sBp[br*BP_COLS + lx];
            u64 w2[11];
            #pragma unroll
            for (int s = 0; s < 11; s++){
                u64 D2 = fma2_(C2[s], NEG2_2, add2_(Bp2[j], Brow[s]));
                float d0 = fmaxf(lo_(D2), 0.f);
                float d1 = fmaxf(hi_(D2), 0.f);
                float w0 = fex2_a(fsqrt_a(d0) * KEXP);
                float w1 = fex2_a(fsqrt_a(d1) * KEXP);
                u64 w = pk_(w0, w1);
                w2[s] = w;
                aw2[j] = add2_(aw2[j], w);
            }
            #pragma unroll
            for (int ch = 0; ch < 3; ch++){
                const unsigned* Xrow = &xh[ch*XH_PLANE + br*BP_COLS + lx];
                u64 acc = (ch==0) ? a02[j] : (ch==1) ? a12[j] : a22[j];
                #pragma unroll
                for (int s = 0; s < 11; s++){
                    unsigned hx = Xrow[s];
                    float2 xv = __half22float2(*reinterpret_cast<const __half2*>(&hx));
                    acc = fma2_(w2[s], pk_(xv.x, xv.y), acc);
                }
                if (ch==0) a02[j] = acc; else if (ch==1) a12[j] = acc; else a22[j] = acc;
            }
        }
        __syncthreads();   // rcS reused next sy
    }

    // ---- epilogue: columns (c0+lx, c0+lx+16) ----
    #pragma unroll
    for (int j = 0; j < RPT; j++){
        float rw0 = frcp_a(lo_(aw2[j]));
        float rw1 = frcp_a(hi_(aw2[j]));
        int gr = r0 + trow + j;
        size_t o = (size_t)n*3*HW + ((size_t)gr << 9) + c0 + lx;
        out[o]           = __saturatef(lo_(a02[j])*rw0);
        out[o+16]        = __saturatef(hi_(a02[j])*rw1);
        out[o+HW]        = __saturatef(lo_(a12[j])*rw0);
        out[o+HW+16]     = __saturatef(hi_(a12[j])*rw1);
        out[o+2*HW]      = __saturatef(lo_(a22[j])*rw0);
        out[o+2*HW+16]   = __saturatef(hi_(a22[j])*rw1);
    }
}

extern "C" void kernel_launch(void* const* d_in, const int* in_sizes, int n_in,
                              void* d_out, int out_size){
    const float* x = (const float*)d_in[0];
    float* out = (float*)d_out;
    (void)in_sizes; (void)n_in; (void)out_size;

    cudaFuncSetAttribute(nlm_kernel, cudaFuncAttributeMaxDynamicSharedMemorySize, SMEM_BYTES);

    dim3 grid(WW/TILE_W, HH/TILE_H, NB);   // 16 x 32 x 2
    dim3 block(LANES, TYv);                // 128 threads
    nlm_kernel<<<grid, block, SMEM_BYTES>>>(x, out);
}